// round 7
// baseline (speedup 1.0000x reference)
#include <cuda_runtime.h>
#include <math.h>

#define B_ROWS 128
#define V_COLS 128256
#define V4 (V_COLS / 4)          // 32064 float4 per row
#define SPLIT 8                  // segments per row
#define SEG_Q (V4 / SPLIT)       // 4008 float4 per segment
#define THREADS 256

// Per-(row,segment) partial argmax results, written unconditionally every
// launch. Counter self-resets to 0 in the last block -> graph-replay safe.
__device__ unsigned long long d_part_g[B_ROWS * SPLIT];
__device__ unsigned long long d_part_s[B_ROWS * SPLIT];
__device__ int d_count[B_ROWS];   // zero-init at load; self-resetting

// Pack (value, index) so 64-bit unsigned max == (max value, then MIN index)
__device__ __forceinline__ unsigned long long pack_key(float v, int idx) {
    unsigned int b = __float_as_uint(v);
    b = (b & 0x80000000u) ? ~b : (b | 0x80000000u);   // order-preserving map
    return ((unsigned long long)b << 32) | (unsigned int)(~idx);
}

__device__ __forceinline__ unsigned long long kmax64(unsigned long long a,
                                                     unsigned long long b) {
    return a > b ? a : b;
}

// w2 = -lg2(uc) with good RELATIVE accuracy on [1e-10, 1-1e-7]:
//  - uc <= 0.96: MUFU lg2 (w2 >= 0.0589 -> rel err ~ 4e-6)
//  - uc  > 0.96: 4-term -log1p(f)/ln2 poly, |f| <= 0.04 (rel err <= 5e-7)
// Both computed, one select -> no divergence.
__device__ __forceinline__ float neg_lg2_acc(float uc) {
    float w_m = fabsf(__log2f(uc));              // lg2(uc) <= 0 -> |.| negates
    float f = uc - 1.0f;
    float p = 0.3606738f;                        //  1/(4 ln2)
    p = fmaf(p, f, -0.4808983f);                 // -1/(3 ln2)
    p = fmaf(p, f,  0.7213475f);                 //  1/(2 ln2)
    p = fmaf(p, f, -1.4426950f);                 // -1/ln2
    float w_p = f * p;                           // = -log1p(f)/ln2  (> 0)
    return (uc > 0.96f) ? w_p : w_m;
}

__global__ __launch_bounds__(THREADS)
void sampler_fused_kernel(const float* __restrict__ logits,
                          const float* __restrict__ temps,
                          const float* __restrict__ u,
                          float* __restrict__ out) {
    const int seg = blockIdx.x;
    const int row = blockIdx.y;

    const float4* __restrict__ lg = reinterpret_cast<const float4*>(logits) + (size_t)row * V4;
    const float4* __restrict__ uu = reinterpret_cast<const float4*>(u)      + (size_t)row * V4;

    const float t_raw = temps[row];
    // argmax(x/t - ln w) == argmax(x/(t*ln2) - lg2 w): fold ln2 into inv
    const float inv2  = 1.4426950408889634f / fmaxf(t_raw, 1e-6f);
    const bool  need_greedy = (t_raw <= 1e-6f);

    const float U_LO = 1e-10f;
    const float U_HI = __uint_as_float(0x3F7FFFFEu);   // float(1 - 1e-7)

    const int q0 = seg * SEG_Q;
    const int q1 = q0 + SEG_Q;

    float bg = __int_as_float(0xFF800000);  // -inf
    int   bgi = 0;
    float bs = __int_as_float(0xFF800000);
    int   bsi = 0;

    if (need_greedy) {
        // Rare path (temps ~ U[0,1)): also track raw-logits argmax
        for (int q = q0 + threadIdx.x; q < q1; q += THREADS) {
            float4 l4 = __ldcs(lg + q);
            float4 u4 = __ldcs(uu + q);
            float lv[4] = {l4.x, l4.y, l4.z, l4.w};
            float uv[4] = {u4.x, u4.y, u4.z, u4.w};
            const int base = q << 2;
            #pragma unroll
            for (int j = 0; j < 4; j++) {
                float x = lv[j];
                if (x > bg) { bg = x; bgi = base + j; }
                float uc  = fminf(fmaxf(uv[j], U_LO), U_HI);
                float w2  = neg_lg2_acc(uc);
                float l2w = __log2f(w2);
                float v   = fmaf(x, inv2, -l2w);
                if (v > bs) { bs = v; bsi = base + j; }
            }
        }
    } else {
        for (int q = q0 + threadIdx.x; q < q1; q += THREADS) {
            float4 l4 = __ldcs(lg + q);
            float4 u4 = __ldcs(uu + q);
            float lv[4] = {l4.x, l4.y, l4.z, l4.w};
            float uv[4] = {u4.x, u4.y, u4.z, u4.w};
            const int base = q << 2;
            #pragma unroll
            for (int j = 0; j < 4; j++) {
                float uc  = fminf(fmaxf(uv[j], U_LO), U_HI);
                float w2  = neg_lg2_acc(uc);            // -lg2(u) > 0
                float l2w = __log2f(w2);                // MUFU
                float v   = fmaf(lv[j], inv2, -l2w);    // gumbel score (lg2 dom)
                if (v > bs) { bs = v; bsi = base + j; }
            }
        }
    }

    // Block reduction on packed keys
    unsigned long long kg = pack_key(bg, bgi);
    unsigned long long ks = pack_key(bs, bsi);

    #pragma unroll
    for (int o = 16; o > 0; o >>= 1) {
        kg = kmax64(kg, __shfl_xor_sync(0xffffffffu, kg, o));
        ks = kmax64(ks, __shfl_xor_sync(0xffffffffu, ks, o));
    }

    __shared__ unsigned long long sg[THREADS / 32];
    __shared__ unsigned long long ss[THREADS / 32];
    const int wid  = threadIdx.x >> 5;
    const int lane = threadIdx.x & 31;
    if (lane == 0) { sg[wid] = kg; ss[wid] = ks; }
    __syncthreads();

    if (threadIdx.x == 0) {
        #pragma unroll
        for (int i = 1; i < THREADS / 32; i++) {
            kg = kmax64(kg, sg[i]);
            ks = kmax64(ks, ss[i]);
        }
        d_part_g[row * SPLIT + seg] = kg;
        d_part_s[row * SPLIT + seg] = ks;

        __threadfence();                       // publish partials
        int old = atomicAdd(&d_count[row], 1);
        if (old == SPLIT - 1) {
            d_count[row] = 0;                  // self-reset for next replay
            __threadfence();
            unsigned long long mg = 0ull, ms = 0ull;
            #pragma unroll
            for (int i = 0; i < SPLIT; i++) {
                mg = kmax64(mg, d_part_g[row * SPLIT + i]);
                ms = kmax64(ms, d_part_s[row * SPLIT + i]);
            }
            int ig = (int)~(unsigned int)mg;
            int is = (int)~(unsigned int)ms;
            int idx = need_greedy ? ig : is;
            out[row] = (float)idx;             // output dtype is float32
        }
    }
}

extern "C" void kernel_launch(void* const* d_in, const int* in_sizes, int n_in,
                              void* d_out, int out_size) {
    const float* logits = (const float*)d_in[0];
    const float* temps  = (const float*)d_in[1];
    const float* u      = (const float*)d_in[2];
    float* out = (float*)d_out;

    dim3 grid(SPLIT, B_ROWS);
    sampler_fused_kernel<<<grid, THREADS>>>(logits, temps, u, out);
}

// round 8
// speedup vs baseline: 1.2970x; 1.2970x over previous
#include <cuda_runtime.h>
#include <math.h>

#define B_ROWS 128
#define V_COLS 128256
#define V4 (V_COLS / 4)          // 32064 float4 per row
#define SPLIT 6                  // segments per row (768 CTAs -> single wave @ occ >= 6)
#define SEG_Q (V4 / SPLIT)       // 5344 float4 per segment (exact)
#define THREADS 256

// Per-(row,segment) partial argmax results, written unconditionally every
// launch. Counter self-resets to 0 in the last block -> graph-replay safe.
__device__ unsigned long long d_part_g[B_ROWS * SPLIT];
__device__ unsigned long long d_part_s[B_ROWS * SPLIT];
__device__ int d_count[B_ROWS];   // zero-init at load; self-resetting

// Pack (value, index) so 64-bit unsigned max == (max value, then MIN index)
__device__ __forceinline__ unsigned long long pack_key(float v, int idx) {
    unsigned int b = __float_as_uint(v);
    b = (b & 0x80000000u) ? ~b : (b | 0x80000000u);   // order-preserving map
    return ((unsigned long long)b << 32) | (unsigned int)(~idx);
}

__device__ __forceinline__ unsigned long long kmax64(unsigned long long a,
                                                     unsigned long long b) {
    return a > b ? a : b;
}

// w = -log(uc), accurate in RELATIVE terms everywhere on [1e-10, 1-1e-7]:
//  - u <= 0.96: MUFU lg2 (w >= 0.0408 -> rel err <= ~8e-6)
//  - u  > 0.96: 4-term log1p poly on f = u-1, |f| <= 0.04 (rel err <= 5e-7)
// Both computed, one select -> no divergence.  (Exact R5 form - proven fast.)
__device__ __forceinline__ float neg_log_acc(float uc) {
    float w_m = -__logf(uc);                    // MUFU path
    float f = uc - 1.0f;                        // in (-0.04, 1.2e-7]
    float p = -0.25f;
    p = fmaf(p, f, 0.333333333f);
    p = fmaf(p, f, -0.5f);
    float w_p = -fmaf(f * f, p, f);             // -log1p(f)
    return (uc > 0.96f) ? w_p : w_m;
}

__global__ __launch_bounds__(THREADS)
void sampler_fused_kernel(const float* __restrict__ logits,
                          const float* __restrict__ temps,
                          const float* __restrict__ u,
                          float* __restrict__ out) {
    const int seg = blockIdx.x;
    const int row = blockIdx.y;

    const float4* __restrict__ lg = reinterpret_cast<const float4*>(logits) + (size_t)row * V4;
    const float4* __restrict__ uu = reinterpret_cast<const float4*>(u)      + (size_t)row * V4;

    const float t_raw = temps[row];
    const float inv   = 1.0f / fmaxf(t_raw, 1e-6f);
    const bool  need_greedy = (t_raw <= 1e-6f);

    const float U_LO = 1e-10f;
    const float U_HI = __uint_as_float(0x3F7FFFFEu);   // float(1 - 1e-7)

    const int q0 = seg * SEG_Q;
    const int q1 = q0 + SEG_Q;

    float bg = __int_as_float(0xFF800000);  // -inf
    int   bgi = 0;
    float bs = __int_as_float(0xFF800000);
    int   bsi = 0;

    if (need_greedy) {
        // Rare path (temps ~ U[0,1)): also track raw-logits argmax
        for (int q = q0 + threadIdx.x; q < q1; q += THREADS) {
            float4 l4 = __ldcs(lg + q);
            float4 u4 = __ldcs(uu + q);
            float lv[4] = {l4.x, l4.y, l4.z, l4.w};
            float uv[4] = {u4.x, u4.y, u4.z, u4.w};
            const int base = q << 2;
            #pragma unroll
            for (int j = 0; j < 4; j++) {
                float x = lv[j];
                if (x > bg) { bg = x; bgi = base + j; }
                float uc = fminf(fmaxf(uv[j], U_LO), U_HI);
                float w  = neg_log_acc(uc);
                float g  = -__logf(w);
                float v  = fmaf(x, inv, g);
                if (v > bs) { bs = v; bsi = base + j; }
            }
        }
    } else {
        // Main path: unroll 2 -> ptxas front-batches 4 LDG.128 (MLP 2 -> 4)
        #pragma unroll 2
        for (int q = q0 + threadIdx.x; q < q1; q += THREADS) {
            float4 l4 = __ldcs(lg + q);
            float4 u4 = __ldcs(uu + q);
            float lv[4] = {l4.x, l4.y, l4.z, l4.w};
            float uv[4] = {u4.x, u4.y, u4.z, u4.w};
            const int base = q << 2;
            #pragma unroll
            for (int j = 0; j < 4; j++) {
                float uc = fminf(fmaxf(uv[j], U_LO), U_HI);
                float w  = neg_log_acc(uc);
                float g  = -__logf(w);
                float v  = fmaf(lv[j], inv, g);
                if (v > bs) { bs = v; bsi = base + j; }
            }
        }
    }

    // Block reduction on packed keys
    unsigned long long kg = pack_key(bg, bgi);
    unsigned long long ks = pack_key(bs, bsi);

    #pragma unroll
    for (int o = 16; o > 0; o >>= 1) {
        kg = kmax64(kg, __shfl_xor_sync(0xffffffffu, kg, o));
        ks = kmax64(ks, __shfl_xor_sync(0xffffffffu, ks, o));
    }

    __shared__ unsigned long long sg[THREADS / 32];
    __shared__ unsigned long long ss[THREADS / 32];
    const int wid  = threadIdx.x >> 5;
    const int lane = threadIdx.x & 31;
    if (lane == 0) { sg[wid] = kg; ss[wid] = ks; }
    __syncthreads();

    if (threadIdx.x == 0) {
        #pragma unroll
        for (int i = 1; i < THREADS / 32; i++) {
            kg = kmax64(kg, sg[i]);
            ks = kmax64(ks, ss[i]);
        }
        d_part_g[row * SPLIT + seg] = kg;
        d_part_s[row * SPLIT + seg] = ks;

        __threadfence();                       // publish partials
        int old = atomicAdd(&d_count[row], 1);
        if (old == SPLIT - 1) {
            d_count[row] = 0;                  // self-reset for next replay
            __threadfence();
            unsigned long long mg = 0ull, ms = 0ull;
            #pragma unroll
            for (int i = 0; i < SPLIT; i++) {
                mg = kmax64(mg, d_part_g[row * SPLIT + i]);
                ms = kmax64(ms, d_part_s[row * SPLIT + i]);
            }
            int ig = (int)~(unsigned int)mg;
            int is = (int)~(unsigned int)ms;
            int idx = need_greedy ? ig : is;
            out[row] = (float)idx;             // output dtype is float32
        }
    }
}

extern "C" void kernel_launch(void* const* d_in, const int* in_sizes, int n_in,
                              void* d_out, int out_size) {
    const float* logits = (const float*)d_in[0];
    const float* temps  = (const float*)d_in[1];
    const float* u      = (const float*)d_in[2];
    float* out = (float*)d_out;

    dim3 grid(SPLIT, B_ROWS);
    sampler_fused_kernel<<<grid, THREADS>>>(logits, temps, u, out);
}

// round 10
// speedup vs baseline: 1.3597x; 1.0483x over previous
#include <cuda_runtime.h>
#include <math.h>

#define B_ROWS 128
#define V_COLS 128256
#define V4 (V_COLS / 4)          // 32064 float4 per row
#define SPLIT 6                  // 768 CTAs -> single wave at occ >= 6
#define SEG_Q (V4 / SPLIT)       // 5344 float4 per segment (exact)
#define THREADS 256

// Per-(row,segment) partial argmax results, written unconditionally every
// launch. Counter self-resets to 0 in the last block -> graph-replay safe.
__device__ unsigned long long d_part_g[B_ROWS * SPLIT];
__device__ unsigned long long d_part_s[B_ROWS * SPLIT];
__device__ int d_count[B_ROWS];   // zero-init at load; self-resetting

// Pack (value, index) so 64-bit unsigned max == (max value, then MIN index)
__device__ __forceinline__ unsigned long long pack_key(float v, int idx) {
    unsigned int b = __float_as_uint(v);
    b = (b & 0x80000000u) ? ~b : (b | 0x80000000u);   // order-preserving map
    return ((unsigned long long)b << 32) | (unsigned int)(~idx);
}

__device__ __forceinline__ unsigned long long kmax64(unsigned long long a,
                                                     unsigned long long b) {
    return a > b ? a : b;
}

// w = -log(uc), accurate in RELATIVE terms everywhere on [1e-10, 1-1e-7]:
//  - u <= 0.96: MUFU lg2 (w >= 0.0408 -> rel err <= ~8e-6)
//  - u  > 0.96: 4-term log1p poly on f = u-1, |f| <= 0.04 (rel err <= 5e-7)
// Both computed, one select -> no divergence.  (Exact R5 form - proven.)
__device__ __forceinline__ float neg_log_acc(float uc) {
    float w_m = -__logf(uc);                    // MUFU path
    float f = uc - 1.0f;                        // in (-0.04, 1.2e-7]
    float p = -0.25f;
    p = fmaf(p, f, 0.333333333f);
    p = fmaf(p, f, -0.5f);
    float w_p = -fmaf(f * f, p, f);             // -log1p(f)
    return (uc > 0.96f) ? w_p : w_m;
}

// Gumbel score for one element (independent of reduction state)
__device__ __forceinline__ float score1(float x, float uv, float inv) {
    const float U_LO = 1e-10f;
    const float U_HI = __uint_as_float(0x3F7FFFFEu);   // float(1 - 1e-7)
    float uc = fminf(fmaxf(uv, U_LO), U_HI);
    float w  = neg_log_acc(uc);
    float g  = -__logf(w);
    return fmaf(x, inv, g);
}

// Process one float4 pair: compute 4 independent scores, tree-reduce to one
// (strict > keeps the LOWER index on ties), then a single guarded update.
__device__ __forceinline__ void body4(float4 l4, float4 u4, int base, float inv,
                                      float& bs, int& bsi) {
    float v0 = score1(l4.x, u4.x, inv);
    float v1 = score1(l4.y, u4.y, inv);
    float v2 = score1(l4.z, u4.z, inv);
    float v3 = score1(l4.w, u4.w, inv);

    float m01 = v0; int i01 = 0;
    if (v1 > m01) { m01 = v1; i01 = 1; }
    float m23 = v2; int i23 = 2;
    if (v3 > m23) { m23 = v3; i23 = 3; }
    float m = m01;  int im = i01;
    if (m23 > m)  { m = m23;  im = i23; }

    if (m > bs) { bs = m; bsi = base + im; }
}

__global__ __launch_bounds__(THREADS, 6)
void sampler_fused_kernel(const float* __restrict__ logits,
                          const float* __restrict__ temps,
                          const float* __restrict__ u,
                          float* __restrict__ out) {
    const int seg = blockIdx.x;
    const int row = blockIdx.y;

    const float4* __restrict__ lg = reinterpret_cast<const float4*>(logits) + (size_t)row * V4;
    const float4* __restrict__ uu = reinterpret_cast<const float4*>(u)      + (size_t)row * V4;

    const float t_raw = temps[row];
    const float inv   = 1.0f / fmaxf(t_raw, 1e-6f);
    const bool  need_greedy = (t_raw <= 1e-6f);

    const int q0 = seg * SEG_Q;
    const int q1 = q0 + SEG_Q;

    float bg = __int_as_float(0xFF800000);  // -inf
    int   bgi = 0;
    float bs = __int_as_float(0xFF800000);
    int   bsi = 0;

    if (need_greedy) {
        // Rare path (temps ~ U[0,1)): also track raw-logits argmax
        for (int q = q0 + threadIdx.x; q < q1; q += THREADS) {
            float4 l4 = __ldcs(lg + q);
            float4 u4 = __ldcs(uu + q);
            const int base = q << 2;
            float lv[4] = {l4.x, l4.y, l4.z, l4.w};
            #pragma unroll
            for (int j = 0; j < 4; j++)
                if (lv[j] > bg) { bg = lv[j]; bgi = base + j; }
            body4(l4, u4, base, inv, bs, bsi);
        }
    } else {
        // Software pipeline: next iteration's loads issue before this body.
        int q = q0 + threadIdx.x;               // always < q1 (THREADS <= SEG_Q)
        float4 lc = __ldcs(lg + q);
        float4 uc = __ldcs(uu + q);
        for (int qn = q + THREADS; qn < q1; qn += THREADS) {
            float4 ln = __ldcs(lg + qn);
            float4 un = __ldcs(uu + qn);
            body4(lc, uc, q << 2, inv, bs, bsi);
            lc = ln; uc = un; q = qn;
        }
        body4(lc, uc, q << 2, inv, bs, bsi);
    }

    // Block reduction on packed keys
    unsigned long long kg = pack_key(bg, bgi);
    unsigned long long ks = pack_key(bs, bsi);

    #pragma unroll
    for (int o = 16; o > 0; o >>= 1) {
        kg = kmax64(kg, __shfl_xor_sync(0xffffffffu, kg, o));
        ks = kmax64(ks, __shfl_xor_sync(0xffffffffu, ks, o));
    }

    __shared__ unsigned long long sg[THREADS / 32];
    __shared__ unsigned long long ss[THREADS / 32];
    const int wid  = threadIdx.x >> 5;
    const int lane = threadIdx.x & 31;
    if (lane == 0) { sg[wid] = kg; ss[wid] = ks; }
    __syncthreads();

    if (threadIdx.x == 0) {
        #pragma unroll
        for (int i = 1; i < THREADS / 32; i++) {
            kg = kmax64(kg, sg[i]);
            ks = kmax64(ks, ss[i]);
        }
        d_part_g[row * SPLIT + seg] = kg;
        d_part_s[row * SPLIT + seg] = ks;

        __threadfence();                       // publish partials
        int old = atomicAdd(&d_count[row], 1);
        if (old == SPLIT - 1) {
            d_count[row] = 0;                  // self-reset for next replay
            __threadfence();
            unsigned long long mg = 0ull, ms = 0ull;
            #pragma unroll
            for (int i = 0; i < SPLIT; i++) {
                mg = kmax64(mg, d_part_g[row * SPLIT + i]);
                ms = kmax64(ms, d_part_s[row * SPLIT + i]);
            }
            int ig = (int)~(unsigned int)mg;
            int is = (int)~(unsigned int)ms;
            int idx = need_greedy ? ig : is;
            out[row] = (float)idx;             // output dtype is float32
        }
    }
}

extern "C" void kernel_launch(void* const* d_in, const int* in_sizes, int n_in,
                              void* d_out, int out_size) {
    const float* logits = (const float*)d_in[0];
    const float* temps  = (const float*)d_in[1];
    const float* u      = (const float*)d_in[2];
    float* out = (float*)d_out;

    dim3 grid(SPLIT, B_ROWS);
    sampler_fused_kernel<<<grid, THREADS>>>(logits, temps, u, out);
}